// round 14
// baseline (speedup 1.0000x reference)
#include <cuda_runtime.h>
#include <cuda_bf16.h>
#include <cstdint>

#define DDIM   128
#define TILE_M 64
#define NTH    384            // 4 compute warps + 8 epilogue warps

// ---- smem layout (bytes) ----
#define A_STRIDE 272                 // bf16 row: 256 data + 16 pad
#define ABUF     34816               // one A buffer pair (hi 17408 + lo 17408)
#define AL_REL   17408
#define WL_OFF   (2 * ABUF)          // 69632: W_lo 128 rows
#define D_OFF    (WL_OFF + 128 * A_STRIDE)   // 104448
#define DST      132                 // D row stride (floats)
#define DBUF_SZ  (TILE_M * DST * 4)  // 33792
#define SMEM_TOTAL (D_OFF + 2 * DBUF_SZ + 128)  // ~172160

// named barrier ids (id+p for the pair)
#define AFULL0 1
#define AFREE0 3
#define DFULL0 5
#define DFREE0 7

__device__ __forceinline__ uint32_t s2u(const void* p) {
    return (uint32_t)__cvta_generic_to_shared(p);
}
__device__ __forceinline__ void bsync(int id) {
    asm volatile("bar.sync %0, %1;" :: "r"(id), "r"(NTH) : "memory");
}
__device__ __forceinline__ void barrive(int id) {
    asm volatile("bar.arrive %0, %1;" :: "r"(id), "r"(NTH) : "memory");
}
__device__ __forceinline__ void mma_bf16(float& d0, float& d1, float& d2, float& d3,
                                         uint32_t a0, uint32_t a1, uint32_t a2, uint32_t a3,
                                         uint32_t b0, uint32_t b1) {
    asm volatile("mma.sync.aligned.m16n8k16.row.col.f32.bf16.bf16.f32 "
                 "{%0,%1,%2,%3}, {%4,%5,%6,%7}, {%8,%9}, {%0,%1,%2,%3};"
                 : "+f"(d0), "+f"(d1), "+f"(d2), "+f"(d3)
                 : "r"(a0), "r"(a1), "r"(a2), "r"(a3), "r"(b0), "r"(b1));
}
__device__ __forceinline__ void ldmx4(uint32_t& r0, uint32_t& r1, uint32_t& r2, uint32_t& r3,
                                      uint32_t addr) {
    asm volatile("ldmatrix.sync.aligned.m8n8.x4.shared.b16 {%0,%1,%2,%3}, [%4];"
                 : "=r"(r0), "=r"(r1), "=r"(r2), "=r"(r3) : "r"(addr));
}
__device__ __forceinline__ void split2(float2 x, uint32_t& h, uint32_t& l) {
    __nv_bfloat16 h0 = __float2bfloat16_rn(x.x);
    __nv_bfloat16 h1 = __float2bfloat16_rn(x.y);
    __nv_bfloat16 l0 = __float2bfloat16_rn(x.x - __bfloat162float(h0));
    __nv_bfloat16 l1 = __float2bfloat16_rn(x.y - __bfloat162float(h1));
    __nv_bfloat162 hh = __halves2bfloat162(h0, h1);
    __nv_bfloat162 ll = __halves2bfloat162(l0, l1);
    h = *(uint32_t*)&hh;
    l = *(uint32_t*)&ll;
}
__device__ __forceinline__ uint2 hi4(float4 x) {
    __nv_bfloat162 a = __halves2bfloat162(__float2bfloat16_rn(x.x), __float2bfloat16_rn(x.y));
    __nv_bfloat162 b = __halves2bfloat162(__float2bfloat16_rn(x.z), __float2bfloat16_rn(x.w));
    return make_uint2(*(uint32_t*)&a, *(uint32_t*)&b);
}
__device__ __forceinline__ uint2 lo4(float4 x) {
    float lx = x.x - __bfloat162float(__float2bfloat16_rn(x.x));
    float ly = x.y - __bfloat162float(__float2bfloat16_rn(x.y));
    float lz = x.z - __bfloat162float(__float2bfloat16_rn(x.z));
    float lw = x.w - __bfloat162float(__float2bfloat16_rn(x.w));
    __nv_bfloat162 a = __halves2bfloat162(__float2bfloat16_rn(lx), __float2bfloat16_rn(ly));
    __nv_bfloat162 b = __halves2bfloat162(__float2bfloat16_rn(lz), __float2bfloat16_rn(lw));
    return make_uint2(*(uint32_t*)&a, *(uint32_t*)&b);
}

extern "C" __global__ void __launch_bounds__(NTH, 1)
hh_ws_kernel(const float* __restrict__ z, const float* __restrict__ v,
             const float* __restrict__ W, const float* __restrict__ b,
             float* __restrict__ out, int B)
{
    extern __shared__ char sm[];

    const int tid  = threadIdx.x;
    const int w    = tid >> 5;
    const int lane = tid & 31;
    const uint32_t sm_u = s2u(sm);

    // ---- one-time: W_lo -> smem (all 384 threads) ----
    for (int it = 0; it < 22; it++) {
        int p = tid + it * NTH;
        if (p < 128 * 64) {
            int row = p >> 6;
            int kp  = p & 63;
            float2 x = *(const float2*)&W[row * DDIM + kp * 2];
            uint32_t h, l;
            split2(x, h, l);
            *(uint32_t*)(sm + WL_OFF + row * A_STRIDE + kp * 4) = l;
        }
    }
    __syncthreads();

    const int ntiles = B / TILE_M;
    const int G = (int)gridDim.x;

    if (tid < 128) {
        // ================= COMPUTE ROLE (warps 0-3, 1/SMSP) =================
        const int cw = w;                // 0..3
        const int n0 = cw * 32;
        const int qk = (lane & 3) * 2;
        const int qr = lane >> 2;

        const uint32_t a_lane = (uint32_t)(lane & 15) * A_STRIDE + (uint32_t)(lane >> 4) * 16;
        const int mi = lane >> 3;
        const int r8 = lane & 7;
        const uint32_t wlob0 = sm_u + WL_OFF
                             + (uint32_t)(n0 + (mi >> 1) * 8 + r8) * A_STRIDE
                             + (uint32_t)(mi & 1) * 16;
        const uint32_t wlob1 = wlob0 + 16u * A_STRIDE;

        // W_hi fragments resident in registers (loaded straight from gmem)
        uint32_t bh[4][8][2];
        #pragma unroll
        for (int nt = 0; nt < 4; nt++) {
            const int n = n0 + nt * 8 + qr;
            #pragma unroll
            for (int kk = 0; kk < 8; kk++) {
                uint32_t l0d, l1d;
                float2 x0 = *(const float2*)&W[n * DDIM + kk * 16 + qk];
                float2 x1 = *(const float2*)&W[n * DDIM + kk * 16 + qk + 8];
                split2(x0, bh[nt][kk][0], l0d);
                split2(x1, bh[nt][kk][1], l1d);
            }
        }
        barrive(AFREE0 + 1);   // A buffer 1 starts free

        int p = 0;
        for (int tile = blockIdx.x; tile < ntiles; tile += G, p ^= 1) {
            bsync(AFULL0 + p);
            const uint32_t ahib = sm_u + (uint32_t)p * ABUF + a_lane;
            const uint32_t alob = ahib + AL_REL;

            float acc[4][4][4];
            #pragma unroll
            for (int mt = 0; mt < 4; mt++)
                #pragma unroll
                for (int nt = 0; nt < 4; nt++)
                    #pragma unroll
                    for (int i = 0; i < 4; i++) acc[mt][nt][i] = 0.f;

            #pragma unroll
            for (int kk = 0; kk < 8; kk++) {
                uint32_t blf[8];
                ldmx4(blf[0], blf[1], blf[2], blf[3], wlob0 + (uint32_t)kk * 32);
                ldmx4(blf[4], blf[5], blf[6], blf[7], wlob1 + (uint32_t)kk * 32);
                #pragma unroll
                for (int mt = 0; mt < 4; mt++) {
                    uint32_t ah0, ah1, ah2, ah3, al0, al1, al2, al3;
                    const uint32_t off = (uint32_t)mt * (16 * A_STRIDE) + (uint32_t)kk * 32;
                    ldmx4(ah0, ah1, ah2, ah3, ahib + off);
                    ldmx4(al0, al1, al2, al3, alob + off);
                    #pragma unroll
                    for (int nt = 0; nt < 4; nt++) {
                        mma_bf16(acc[mt][nt][0], acc[mt][nt][1], acc[mt][nt][2], acc[mt][nt][3],
                                 ah0, ah1, ah2, ah3, bh[nt][kk][0], bh[nt][kk][1]);
                        mma_bf16(acc[mt][nt][0], acc[mt][nt][1], acc[mt][nt][2], acc[mt][nt][3],
                                 ah0, ah1, ah2, ah3, blf[nt * 2], blf[nt * 2 + 1]);
                        mma_bf16(acc[mt][nt][0], acc[mt][nt][1], acc[mt][nt][2], acc[mt][nt][3],
                                 al0, al1, al2, al3, bh[nt][kk][0], bh[nt][kk][1]);
                    }
                }
            }
            barrive(AFREE0 + p);       // A[p] reads complete

            bsync(DFREE0 + p);         // D[p] free
            float* D = (float*)(sm + D_OFF + p * DBUF_SZ);
            #pragma unroll
            for (int mt = 0; mt < 4; mt++) {
                const int rt = mt * 16 + qr;
                #pragma unroll
                for (int nt = 0; nt < 4; nt++) {
                    *(float2*)&D[rt * DST + n0 + nt * 8 + qk] =
                        make_float2(acc[mt][nt][0], acc[mt][nt][1]);
                    *(float2*)&D[(rt + 8) * DST + n0 + nt * 8 + qk] =
                        make_float2(acc[mt][nt][2], acc[mt][nt][3]);
                }
            }
            barrive(DFULL0 + p);
        }
    } else {
        // ================= EPILOGUE ROLE (warps 4-11, 2/SMSP) =================
        const int et   = tid - 128;      // 0..255
        const int ew   = w - 4;          // 0..7
        const int row0 = ew * 8;
        const float4 bsr = *(const float4*)&b[lane * 4];

        barrive(DFREE0);
        barrive(DFREE0 + 1);

        // prologue: v(t0) -> convert -> A[0]
        float4 vreg[8];
        const int t0 = (int)blockIdx.x;
        {
            const float* src = v + (size_t)t0 * TILE_M * DDIM;
            #pragma unroll
            for (int j = 0; j < 8; j++)
                vreg[j] = *(const float4*)(src + (size_t)(et + j * 256) * 4);
            #pragma unroll
            for (int j = 0; j < 8; j++) {
                int c   = et + j * 256;
                int row = c >> 5;
                int k8  = (c & 31) * 8;
                *(uint2*)(sm + row * A_STRIDE + k8) = hi4(vreg[j]);
                *(uint2*)(sm + AL_REL + row * A_STRIDE + k8) = lo4(vreg[j]);
            }
            barrive(AFULL0);
            if (t0 + G < ntiles) {
                const float* s2 = v + (size_t)(t0 + G) * TILE_M * DDIM;
                #pragma unroll
                for (int j = 0; j < 8; j++)
                    vreg[j] = *(const float4*)(s2 + (size_t)(et + j * 256) * 4);
            }
        }

        int p = 0;
        for (int tile = t0; tile < ntiles; tile += G, p ^= 1) {
            const size_t tb = (size_t)tile * TILE_M * DDIM;
            const int nxt = tile + G;

            // convert v(nxt) -> A[p^1] (overlaps compute MMA on A[p])
            if (nxt < ntiles) {
                bsync(AFREE0 + (p ^ 1));
                const uint32_t ab = (uint32_t)(p ^ 1) * ABUF;
                #pragma unroll
                for (int j = 0; j < 8; j++) {
                    int c   = et + j * 256;
                    int row = c >> 5;
                    int k8  = (c & 31) * 8;
                    *(uint2*)(sm + ab + row * A_STRIDE + k8) = hi4(vreg[j]);
                    *(uint2*)(sm + ab + AL_REL + row * A_STRIDE + k8) = lo4(vreg[j]);
                }
                barrive(AFULL0 + (p ^ 1));
                const int t2 = tile + 2 * G;
                if (t2 < ntiles) {
                    const float* s2 = v + (size_t)t2 * TILE_M * DDIM;
                    #pragma unroll
                    for (int j = 0; j < 8; j++)
                        vreg[j] = *(const float4*)(s2 + (size_t)(et + j * 256) * 4);
                }
            }

            // z rows early (overlaps the DFULL wait)
            float4 zreg[8];
            #pragma unroll
            for (int r = 0; r < 8; r++)
                zreg[r] = *(const float4*)(z + tb + (size_t)(row0 + r) * DDIM + lane * 4);

            bsync(DFULL0 + p);
            const float* D = (const float*)(sm + D_OFF + p * DBUF_SZ);

            #pragma unroll
            for (int r = 0; r < 8; r++) {
                const int row = row0 + r;
                float4 d4 = *(const float4*)&D[row * DST + lane * 4];
                float vn0 = d4.x + bsr.x;
                float vn1 = d4.y + bsr.y;
                float vn2 = d4.z + bsr.z;
                float vn3 = d4.w + bsr.w;
                float4 z4 = zreg[r];
                float dt = vn0 * z4.x + vn1 * z4.y + vn2 * z4.z + vn3 * z4.w;
                float nm = vn0 * vn0 + vn1 * vn1 + vn2 * vn2 + vn3 * vn3;
                #pragma unroll
                for (int s = 16; s; s >>= 1) {
                    dt += __shfl_xor_sync(0xffffffffu, dt, s);
                    nm += __shfl_xor_sync(0xffffffffu, nm, s);
                }
                const float sc = 2.0f * dt / nm;
                float4 o;
                o.x = z4.x - sc * vn0;
                o.y = z4.y - sc * vn1;
                o.z = z4.z - sc * vn2;
                o.w = z4.w - sc * vn3;
                *(float4*)(out + tb + (size_t)row * DDIM + lane * 4) = o;
            }
            barrive(DFREE0 + p);
        }
    }
}

extern "C" void kernel_launch(void* const* d_in, const int* in_sizes, int n_in,
                              void* d_out, int out_size) {
    const float* z = (const float*)d_in[0];
    const float* v = (const float*)d_in[1];
    const float* W = (const float*)d_in[2];
    const float* b = (const float*)d_in[3];
    float* out = (float*)d_out;

    const int B = in_sizes[0] / DDIM;

    cudaFuncSetAttribute(hh_ws_kernel, cudaFuncAttributeMaxDynamicSharedMemorySize, SMEM_TOTAL);
    hh_ws_kernel<<<148, NTH, SMEM_TOTAL>>>(z, v, W, b, out, B);
}

// round 15
// speedup vs baseline: 1.0033x; 1.0033x over previous
#include <cuda_runtime.h>
#include <cuda_bf16.h>
#include <cstdint>

#define DDIM   128
#define TILE_M 64
#define NTH    512            // 8 compute warps + 8 epilogue warps

// ---- smem layout (bytes) ----
#define A_STRIDE 272                 // bf16 row: 256 data + 16 pad
#define ABUF     34816               // one A buffer pair (hi 17408 + lo 17408)
#define AL_REL   17408
#define WL_OFF   (2 * ABUF)          // 69632: W_lo 128 rows
#define D_OFF    (WL_OFF + 128 * A_STRIDE)   // 104448
#define DST      132                 // D row stride (floats)
#define DBUF_SZ  (TILE_M * DST * 4)  // 33792
#define SMEM_TOTAL (D_OFF + 2 * DBUF_SZ + 128)  // 172160

// named barrier ids (id+p for the buffer pair)
#define AFULL0 1
#define AFREE0 3
#define DFULL0 5
#define DFREE0 7

__device__ __forceinline__ uint32_t s2u(const void* p) {
    return (uint32_t)__cvta_generic_to_shared(p);
}
__device__ __forceinline__ void bsync(int id) {
    asm volatile("bar.sync %0, %1;" :: "r"(id), "r"(NTH) : "memory");
}
__device__ __forceinline__ void barrive(int id) {
    asm volatile("bar.arrive %0, %1;" :: "r"(id), "r"(NTH) : "memory");
}
__device__ __forceinline__ void mma_bf16(float& d0, float& d1, float& d2, float& d3,
                                         uint32_t a0, uint32_t a1, uint32_t a2, uint32_t a3,
                                         uint32_t b0, uint32_t b1) {
    asm volatile("mma.sync.aligned.m16n8k16.row.col.f32.bf16.bf16.f32 "
                 "{%0,%1,%2,%3}, {%4,%5,%6,%7}, {%8,%9}, {%0,%1,%2,%3};"
                 : "+f"(d0), "+f"(d1), "+f"(d2), "+f"(d3)
                 : "r"(a0), "r"(a1), "r"(a2), "r"(a3), "r"(b0), "r"(b1));
}
__device__ __forceinline__ void ldmx4(uint32_t& r0, uint32_t& r1, uint32_t& r2, uint32_t& r3,
                                      uint32_t addr) {
    asm volatile("ldmatrix.sync.aligned.m8n8.x4.shared.b16 {%0,%1,%2,%3}, [%4];"
                 : "=r"(r0), "=r"(r1), "=r"(r2), "=r"(r3) : "r"(addr));
}
__device__ __forceinline__ void split2(float2 x, uint32_t& h, uint32_t& l) {
    __nv_bfloat16 h0 = __float2bfloat16_rn(x.x);
    __nv_bfloat16 h1 = __float2bfloat16_rn(x.y);
    __nv_bfloat16 l0 = __float2bfloat16_rn(x.x - __bfloat162float(h0));
    __nv_bfloat16 l1 = __float2bfloat16_rn(x.y - __bfloat162float(h1));
    __nv_bfloat162 hh = __halves2bfloat162(h0, h1);
    __nv_bfloat162 ll = __halves2bfloat162(l0, l1);
    h = *(uint32_t*)&hh;
    l = *(uint32_t*)&ll;
}
__device__ __forceinline__ uint2 hi4(float4 x) {
    __nv_bfloat162 a = __halves2bfloat162(__float2bfloat16_rn(x.x), __float2bfloat16_rn(x.y));
    __nv_bfloat162 b = __halves2bfloat162(__float2bfloat16_rn(x.z), __float2bfloat16_rn(x.w));
    return make_uint2(*(uint32_t*)&a, *(uint32_t*)&b);
}
__device__ __forceinline__ uint2 lo4(float4 x) {
    float lx = x.x - __bfloat162float(__float2bfloat16_rn(x.x));
    float ly = x.y - __bfloat162float(__float2bfloat16_rn(x.y));
    float lz = x.z - __bfloat162float(__float2bfloat16_rn(x.z));
    float lw = x.w - __bfloat162float(__float2bfloat16_rn(x.w));
    __nv_bfloat162 a = __halves2bfloat162(__float2bfloat16_rn(lx), __float2bfloat16_rn(ly));
    __nv_bfloat162 b = __halves2bfloat162(__float2bfloat16_rn(lz), __float2bfloat16_rn(lw));
    return make_uint2(*(uint32_t*)&a, *(uint32_t*)&b);
}

extern "C" __global__ void __launch_bounds__(NTH, 1)
hh_ws_kernel(const float* __restrict__ z, const float* __restrict__ v,
             const float* __restrict__ W, const float* __restrict__ b,
             float* __restrict__ out, int B)
{
    extern __shared__ char sm[];

    const int tid  = threadIdx.x;
    const int w    = tid >> 5;
    const int lane = tid & 31;
    const uint32_t sm_u = s2u(sm);

    // ---- one-time: W_lo -> smem (all 512 threads) ----
    #pragma unroll
    for (int it = 0; it < 16; it++) {
        int p   = tid + it * NTH;        // pair index over 128x64
        int row = p >> 6;
        int kp  = p & 63;
        float2 x = *(const float2*)&W[row * DDIM + kp * 2];
        uint32_t h, l;
        split2(x, h, l);
        *(uint32_t*)(sm + WL_OFF + row * A_STRIDE + kp * 4) = l;
    }
    __syncthreads();

    const int ntiles = B / TILE_M;
    const int G = (int)gridDim.x;

    if (tid < 256) {
        // ========== COMPUTE ROLE (warps 0-7, 2/SMSP): pure MMA ==========
        const int cg = w & 3;            // 32-col group
        const int mg = w >> 2;           // 32-row group
        const int n0 = cg * 32;
        const int qk = (lane & 3) * 2;
        const int qr = lane >> 2;

        const uint32_t a_lane = (uint32_t)(mg * 32 + (lane & 15)) * A_STRIDE
                              + (uint32_t)(lane >> 4) * 16;
        const int mi = lane >> 3;
        const int r8 = lane & 7;
        const uint32_t wlob0 = sm_u + WL_OFF
                             + (uint32_t)(n0 + (mi >> 1) * 8 + r8) * A_STRIDE
                             + (uint32_t)(mi & 1) * 16;
        const uint32_t wlob1 = wlob0 + 16u * A_STRIDE;

        // W_hi fragments resident in registers (direct from gmem; L2-hot)
        uint32_t bh[4][8][2];
        #pragma unroll
        for (int nt = 0; nt < 4; nt++) {
            const int n = n0 + nt * 8 + qr;
            #pragma unroll
            for (int kk = 0; kk < 8; kk++) {
                uint32_t l0d, l1d;
                float2 x0 = *(const float2*)&W[n * DDIM + kk * 16 + qk];
                float2 x1 = *(const float2*)&W[n * DDIM + kk * 16 + qk + 8];
                split2(x0, bh[nt][kk][0], l0d);
                split2(x1, bh[nt][kk][1], l1d);
            }
        }
        barrive(AFREE0 + 1);   // A buffer 1 starts free

        int p = 0;
        for (int tile = blockIdx.x; tile < ntiles; tile += G, p ^= 1) {
            bsync(AFULL0 + p);
            const uint32_t ahib = sm_u + (uint32_t)p * ABUF + a_lane;
            const uint32_t alob = ahib + AL_REL;

            float acc[2][4][4];
            #pragma unroll
            for (int mt = 0; mt < 2; mt++)
                #pragma unroll
                for (int nt = 0; nt < 4; nt++)
                    #pragma unroll
                    for (int i = 0; i < 4; i++) acc[mt][nt][i] = 0.f;

            #pragma unroll
            for (int kk = 0; kk < 8; kk++) {
                uint32_t blf[8];
                ldmx4(blf[0], blf[1], blf[2], blf[3], wlob0 + (uint32_t)kk * 32);
                ldmx4(blf[4], blf[5], blf[6], blf[7], wlob1 + (uint32_t)kk * 32);
                #pragma unroll
                for (int mt = 0; mt < 2; mt++) {
                    uint32_t ah0, ah1, ah2, ah3, al0, al1, al2, al3;
                    const uint32_t off = (uint32_t)mt * (16 * A_STRIDE) + (uint32_t)kk * 32;
                    ldmx4(ah0, ah1, ah2, ah3, ahib + off);
                    ldmx4(al0, al1, al2, al3, alob + off);
                    #pragma unroll
                    for (int nt = 0; nt < 4; nt++) {
                        mma_bf16(acc[mt][nt][0], acc[mt][nt][1], acc[mt][nt][2], acc[mt][nt][3],
                                 ah0, ah1, ah2, ah3, bh[nt][kk][0], bh[nt][kk][1]);
                        mma_bf16(acc[mt][nt][0], acc[mt][nt][1], acc[mt][nt][2], acc[mt][nt][3],
                                 ah0, ah1, ah2, ah3, blf[nt * 2], blf[nt * 2 + 1]);
                        mma_bf16(acc[mt][nt][0], acc[mt][nt][1], acc[mt][nt][2], acc[mt][nt][3],
                                 al0, al1, al2, al3, bh[nt][kk][0], bh[nt][kk][1]);
                    }
                }
            }
            barrive(AFREE0 + p);       // A[p] reads complete

            bsync(DFREE0 + p);         // D[p] free
            float* D = (float*)(sm + D_OFF + p * DBUF_SZ);
            #pragma unroll
            for (int mt = 0; mt < 2; mt++) {
                const int rt = mg * 32 + mt * 16 + qr;
                #pragma unroll
                for (int nt = 0; nt < 4; nt++) {
                    *(float2*)&D[rt * DST + n0 + nt * 8 + qk] =
                        make_float2(acc[mt][nt][0], acc[mt][nt][1]);
                    *(float2*)&D[(rt + 8) * DST + n0 + nt * 8 + qk] =
                        make_float2(acc[mt][nt][2], acc[mt][nt][3]);
                }
            }
            barrive(DFULL0 + p);
        }
    } else {
        // ========== EPILOGUE ROLE (warps 8-15): v-convert + z + reflect ==========
        const int et   = tid - 256;      // 0..255
        const int ew   = w - 8;          // 0..7
        const int row0 = ew * 8;
        const float4 bsr = *(const float4*)&b[lane * 4];

        barrive(DFREE0);
        barrive(DFREE0 + 1);

        // prologue: v(t0) -> convert -> A[0]
        float4 vreg[8];
        const int t0 = (int)blockIdx.x;
        {
            const float* src = v + (size_t)t0 * TILE_M * DDIM;
            #pragma unroll
            for (int j = 0; j < 8; j++)
                vreg[j] = *(const float4*)(src + (size_t)(et + j * 256) * 4);
            #pragma unroll
            for (int j = 0; j < 8; j++) {
                int c   = et + j * 256;
                int row = c >> 5;
                int k8  = (c & 31) * 8;
                *(uint2*)(sm + row * A_STRIDE + k8) = hi4(vreg[j]);
                *(uint2*)(sm + AL_REL + row * A_STRIDE + k8) = lo4(vreg[j]);
            }
            barrive(AFULL0);
            if (t0 + G < ntiles) {
                const float* s2 = v + (size_t)(t0 + G) * TILE_M * DDIM;
                #pragma unroll
                for (int j = 0; j < 8; j++)
                    vreg[j] = *(const float4*)(s2 + (size_t)(et + j * 256) * 4);
            }
        }

        int p = 0;
        for (int tile = t0; tile < ntiles; tile += G, p ^= 1) {
            const size_t tb = (size_t)tile * TILE_M * DDIM;
            const int nxt = tile + G;

            // convert v(nxt) -> A[p^1] (overlaps compute MMA on A[p])
            if (nxt < ntiles) {
                bsync(AFREE0 + (p ^ 1));
                const uint32_t ab = (uint32_t)(p ^ 1) * ABUF;
                #pragma unroll
                for (int j = 0; j < 8; j++) {
                    int c   = et + j * 256;
                    int row = c >> 5;
                    int k8  = (c & 31) * 8;
                    *(uint2*)(sm + ab + row * A_STRIDE + k8) = hi4(vreg[j]);
                    *(uint2*)(sm + ab + AL_REL + row * A_STRIDE + k8) = lo4(vreg[j]);
                }
                barrive(AFULL0 + (p ^ 1));
                const int t2 = tile + 2 * G;
                if (t2 < ntiles) {
                    const float* s2 = v + (size_t)t2 * TILE_M * DDIM;
                    #pragma unroll
                    for (int j = 0; j < 8; j++)
                        vreg[j] = *(const float4*)(s2 + (size_t)(et + j * 256) * 4);
                }
            }

            // z rows early (overlaps the DFULL wait)
            float4 zreg[8];
            #pragma unroll
            for (int r = 0; r < 8; r++)
                zreg[r] = *(const float4*)(z + tb + (size_t)(row0 + r) * DDIM + lane * 4);

            bsync(DFULL0 + p);
            const float* D = (const float*)(sm + D_OFF + p * DBUF_SZ);

            #pragma unroll
            for (int r = 0; r < 8; r++) {
                const int row = row0 + r;
                float4 d4 = *(const float4*)&D[row * DST + lane * 4];
                float vn0 = d4.x + bsr.x;
                float vn1 = d4.y + bsr.y;
                float vn2 = d4.z + bsr.z;
                float vn3 = d4.w + bsr.w;
                float4 z4 = zreg[r];
                float dt = vn0 * z4.x + vn1 * z4.y + vn2 * z4.z + vn3 * z4.w;
                float nm = vn0 * vn0 + vn1 * vn1 + vn2 * vn2 + vn3 * vn3;
                #pragma unroll
                for (int s = 16; s; s >>= 1) {
                    dt += __shfl_xor_sync(0xffffffffu, dt, s);
                    nm += __shfl_xor_sync(0xffffffffu, nm, s);
                }
                const float sc = 2.0f * dt / nm;
                float4 o;
                o.x = z4.x - sc * vn0;
                o.y = z4.y - sc * vn1;
                o.z = z4.z - sc * vn2;
                o.w = z4.w - sc * vn3;
                *(float4*)(out + tb + (size_t)row * DDIM + lane * 4) = o;
            }
            barrive(DFREE0 + p);
        }
    }
}

extern "C" void kernel_launch(void* const* d_in, const int* in_sizes, int n_in,
                              void* d_out, int out_size) {
    const float* z = (const float*)d_in[0];
    const float* v = (const float*)d_in[1];
    const float* W = (const float*)d_in[2];
    const float* b = (const float*)d_in[3];
    float* out = (float*)d_out;

    const int B = in_sizes[0] / DDIM;

    cudaFuncSetAttribute(hh_ws_kernel, cudaFuncAttributeMaxDynamicSharedMemorySize, SMEM_TOTAL);
    hh_ws_kernel<<<148, NTH, SMEM_TOTAL>>>(z, v, W, b, out, B);
}